// round 5
// baseline (speedup 1.0000x reference)
#include <cuda_runtime.h>

#define N_USER 50000
#define N_ITEM 100000
#define N_TOT  150000
#define EMB    64

// Scratch (allocation-free rule: __device__ globals)
__device__ float g_ego[(size_t)N_TOT * EMB];   // 38.4 MB
__device__ float g_side[(size_t)N_TOT * EMB];  // 38.4 MB

// ---------------------------------------------------------------------------
// ego = concat(user_emb, item_emb)   (float4 vectorized copy)
// ---------------------------------------------------------------------------
__global__ void k_init_ego(const float* __restrict__ ue, const float* __restrict__ ie) {
    size_t i = (size_t)blockIdx.x * blockDim.x + threadIdx.x;
    const size_t nu4 = (size_t)N_USER * EMB / 4;
    const size_t nt4 = (size_t)N_TOT * EMB / 4;
    if (i >= nt4) return;
    float4 v = (i < nu4) ? ((const float4*)ue)[i] : ((const float4*)ie)[i - nu4];
    ((float4*)g_ego)[i] = v;
}

__global__ void k_zero_side() {
    size_t i = (size_t)blockIdx.x * blockDim.x + threadIdx.x;
    const size_t nt4 = (size_t)N_TOT * EMB / 4;
    if (i < nt4) ((float4*)g_side)[i] = make_float4(0.f, 0.f, 0.f, 0.f);
}

// ---------------------------------------------------------------------------
// SpMM scatter: side[rows[e]] += vals[e] * ego[cols[e]]
// 16 threads per edge; float4 gather + 4 atomicAdd (-> RED.E.ADD.F32)
// ---------------------------------------------------------------------------
__global__ void k_spmm(const int* __restrict__ rows, const int* __restrict__ cols,
                       const float* __restrict__ vals, int nnz) {
    long long t = (long long)blockIdx.x * blockDim.x + threadIdx.x;
    int e = (int)(t >> 4);
    int lane = (int)(t & 15);
    if (e >= nnz) return;
    int r = __ldg(rows + e);
    int c = __ldg(cols + e);
    float v = __ldg(vals + e);
    float4 x = ((const float4*)(g_ego + (size_t)c * EMB))[lane];
    float* dst = g_side + (size_t)r * EMB + lane * 4;
    atomicAdd(dst + 0, v * x.x);
    atomicAdd(dst + 1, v * x.y);
    atomicAdd(dst + 2, v * x.z);
    atomicAdd(dst + 3, v * x.w);
}

// ---------------------------------------------------------------------------
// ego = leaky_relu(side @ W + b, 0.2)
// Block: 256 threads, 32 rows. W + bias + the 32 side rows in shared mem.
// thread (rs=tid/64, col=tid%64) computes rows rs, rs+4, ..., rs+28.
// sW[k*64+col]: consecutive cols per warp -> conflict-free; sR[row][k]: broadcast.
// ---------------------------------------------------------------------------
__global__ void k_gemm_act(const float* __restrict__ W, const float* __restrict__ b) {
    __shared__ float sW[EMB * EMB];
    __shared__ float sR[32][EMB];
    __shared__ float sB[EMB];
    int tid = threadIdx.x;

    for (int i = tid; i < EMB * EMB; i += 256) sW[i] = W[i];
    if (tid < EMB) sB[tid] = b[tid];

    int row0 = blockIdx.x * 32;
    for (int i = tid; i < 32 * EMB / 4; i += 256) {
        int rr = i / (EMB / 4);
        size_t gr = (size_t)row0 + rr;
        float4 v = (gr < N_TOT) ? ((const float4*)(g_side + gr * EMB))[i % (EMB / 4)]
                                : make_float4(0.f, 0.f, 0.f, 0.f);
        ((float4*)sR)[i] = v;
    }
    __syncthreads();

    int col = tid & 63;
    int rs  = tid >> 6;  // 0..3
    #pragma unroll
    for (int j = 0; j < 8; j++) {
        int row = rs + j * 4;
        size_t grow = (size_t)row0 + row;
        if (grow >= N_TOT) continue;
        float acc = sB[col];
        #pragma unroll
        for (int k = 0; k < EMB; k++) acc += sR[row][k] * sW[k * EMB + col];
        acc = (acc > 0.f) ? acc : 0.2f * acc;
        g_ego[grow * EMB + col] = acc;
    }
}

// ---------------------------------------------------------------------------
// out[i] = user_emb[users[i]]   (16 threads/row, float4)
// ---------------------------------------------------------------------------
__global__ void k_out_init(const int* __restrict__ users, const float* __restrict__ ue,
                           float* __restrict__ out, int batch) {
    int t = blockIdx.x * blockDim.x + threadIdx.x;
    int i = t >> 4, lane = t & 15;
    if (i >= batch) return;
    int u = users[i];
    ((float4*)out)[(size_t)i * (EMB / 4) + lane] =
        ((const float4*)ue)[(size_t)u * (EMB / 4) + lane];
}

// ---------------------------------------------------------------------------
// out[i] += l2norm(ego[users[i]])   (warp per row, shfl reduce)
// ---------------------------------------------------------------------------
__global__ void k_out_accum(const int* __restrict__ users, float* __restrict__ out, int batch) {
    int t = blockIdx.x * blockDim.x + threadIdx.x;
    int i = t >> 5, lane = t & 31;
    if (i >= batch) return;
    int u = users[i];
    float2 x = ((const float2*)(g_ego + (size_t)u * EMB))[lane];
    float ss = x.x * x.x + x.y * x.y;
    #pragma unroll
    for (int off = 16; off; off >>= 1) ss += __shfl_xor_sync(0xffffffffu, ss, off);
    float inv = 1.0f / fmaxf(sqrtf(ss), 1e-12f);
    float2* o = (float2*)(out + (size_t)i * EMB);
    float2 cur = o[lane];
    cur.x += x.x * inv;
    cur.y += x.y * inv;
    o[lane] = cur;
}

// ---------------------------------------------------------------------------
extern "C" void kernel_launch(void* const* d_in, const int* in_sizes, int n_in,
                              void* d_out, int out_size) {
    const int*   users = (const int*)d_in[0];
    const int*   rows  = (const int*)d_in[1];
    const int*   cols  = (const int*)d_in[2];
    const float* vals  = (const float*)d_in[3];
    const float* ue    = (const float*)d_in[4];
    const float* ie    = (const float*)d_in[5];
    const float* Ws[3] = {(const float*)d_in[6], (const float*)d_in[8],  (const float*)d_in[10]};
    const float* bs[3] = {(const float*)d_in[7], (const float*)d_in[9],  (const float*)d_in[11]};
    int batch = in_sizes[0];
    int nnz   = in_sizes[1];
    float* out = (float*)d_out;

    const int nt4 = N_TOT * EMB / 4;

    k_init_ego<<<(nt4 + 255) / 256, 256>>>(ue, ie);
    k_out_init<<<(batch * 16 + 255) / 256, 256>>>(users, ue, out, batch);

    for (int l = 0; l < 3; l++) {
        k_zero_side<<<(nt4 + 255) / 256, 256>>>();
        long long spmm_threads = (long long)nnz * 16;
        k_spmm<<<(unsigned)((spmm_threads + 255) / 256), 256>>>(rows, cols, vals, nnz);
        k_gemm_act<<<(N_TOT + 31) / 32, 256>>>(Ws[l], bs[l]);
        k_out_accum<<<(batch * 32 + 255) / 256, 256>>>(users, out, batch);
    }
}

// round 7
// speedup vs baseline: 1.0166x; 1.0166x over previous
#include <cuda_runtime.h>

#define N_USER 50000
#define N_ITEM 100000
#define N_TOT  150000
#define EMB    64
#define RPAD   68   // sR row stride: 16B-aligned (68*4=272B) AND conflict-free
                    // (rows differ by 68 floats -> banks {0,4,8,12} for the 4
                    // distinct rows a warp broadcasts from)

// Scratch (allocation-free rule: __device__ globals)
__device__ float g_ego[(size_t)N_TOT * EMB];   // 38.4 MB
__device__ float g_side[(size_t)N_TOT * EMB];  // 38.4 MB

// ---------------------------------------------------------------------------
// ego = concat(user_emb, item_emb)   (float4 vectorized copy)
// ---------------------------------------------------------------------------
__global__ void k_init_ego(const float* __restrict__ ue, const float* __restrict__ ie) {
    size_t i = (size_t)blockIdx.x * blockDim.x + threadIdx.x;
    const size_t nu4 = (size_t)N_USER * EMB / 4;
    const size_t nt4 = (size_t)N_TOT * EMB / 4;
    if (i >= nt4) return;
    float4 v = (i < nu4) ? ((const float4*)ue)[i] : ((const float4*)ie)[i - nu4];
    ((float4*)g_ego)[i] = v;
}

__global__ void k_zero_side() {
    size_t i = (size_t)blockIdx.x * blockDim.x + threadIdx.x;
    const size_t nt4 = (size_t)N_TOT * EMB / 4;
    if (i < nt4) ((float4*)g_side)[i] = make_float4(0.f, 0.f, 0.f, 0.f);
}

// ---------------------------------------------------------------------------
// SpMM scatter: side[rows[e]] += vals[e] * ego[cols[e]]
// 16 threads per edge; float4 gather + ONE vectorized red.global.add.v4.f32
// (sm_90+) -> L1 lane-ops per edge: 80 -> 32.
// ---------------------------------------------------------------------------
__global__ void k_spmm(const int* __restrict__ rows, const int* __restrict__ cols,
                       const float* __restrict__ vals, int nnz) {
    long long t = (long long)blockIdx.x * blockDim.x + threadIdx.x;
    int e = (int)(t >> 4);
    int lane = (int)(t & 15);
    if (e >= nnz) return;
    int r = __ldg(rows + e);
    int c = __ldg(cols + e);
    float v = __ldg(vals + e);
    float4 x = ((const float4*)(g_ego + (size_t)c * EMB))[lane];
    float* dst = g_side + (size_t)r * EMB + lane * 4;
    asm volatile("red.global.add.v4.f32 [%0], {%1, %2, %3, %4};"
                 :: "l"(dst), "f"(v * x.x), "f"(v * x.y), "f"(v * x.z), "f"(v * x.w)
                 : "memory");
}

// ---------------------------------------------------------------------------
// ego = leaky_relu(side @ W + b, 0.2)
// Block: 256 threads, 32 rows/block. Each thread: 1 row x 8 cols.
// Per k-step: 1 broadcast LDS (sR) + 2 LDS.128 (sW) feed 8 FFMAs.
// ---------------------------------------------------------------------------
__global__ void k_gemm_act(const float* __restrict__ W, const float* __restrict__ b) {
    __shared__ float sW[EMB * EMB];
    __shared__ float sR[32][RPAD];
    __shared__ float sB[EMB];
    int tid = threadIdx.x;

    for (int i = tid; i < EMB * EMB; i += 256) sW[i] = W[i];
    if (tid < EMB) sB[tid] = b[tid];

    int row0 = blockIdx.x * 32;
    for (int i = tid; i < 32 * (EMB / 4); i += 256) {
        int rr = i / (EMB / 4);
        int cc = i % (EMB / 4);
        size_t gr = (size_t)row0 + rr;
        float4 v = (gr < N_TOT) ? ((const float4*)(g_side + gr * EMB))[cc]
                                : make_float4(0.f, 0.f, 0.f, 0.f);
        *(float4*)&sR[rr][cc * 4] = v;   // 16B-aligned: rr*272 + cc*16
    }
    __syncthreads();

    int row  = tid >> 3;        // 0..31
    int colg = (tid & 7) * 8;   // 0,8,...,56
    size_t grow = (size_t)row0 + row;
    if (grow >= N_TOT) return;

    float acc[8];
    #pragma unroll
    for (int j = 0; j < 8; j++) acc[j] = sB[colg + j];

    #pragma unroll 8
    for (int k = 0; k < EMB; k++) {
        float r = sR[row][k];
        float4 w0 = *(const float4*)&sW[k * EMB + colg];
        float4 w1 = *(const float4*)&sW[k * EMB + colg + 4];
        acc[0] += r * w0.x;  acc[1] += r * w0.y;
        acc[2] += r * w0.z;  acc[3] += r * w0.w;
        acc[4] += r * w1.x;  acc[5] += r * w1.y;
        acc[6] += r * w1.z;  acc[7] += r * w1.w;
    }

    #pragma unroll
    for (int j = 0; j < 8; j++) acc[j] = (acc[j] > 0.f) ? acc[j] : 0.2f * acc[j];

    float* o = g_ego + grow * EMB + colg;
    *(float4*)o       = make_float4(acc[0], acc[1], acc[2], acc[3]);
    *(float4*)(o + 4) = make_float4(acc[4], acc[5], acc[6], acc[7]);
}

// ---------------------------------------------------------------------------
// out[i] = user_emb[users[i]]   (16 threads/row, float4)
// ---------------------------------------------------------------------------
__global__ void k_out_init(const int* __restrict__ users, const float* __restrict__ ue,
                           float* __restrict__ out, int batch) {
    int t = blockIdx.x * blockDim.x + threadIdx.x;
    int i = t >> 4, lane = t & 15;
    if (i >= batch) return;
    int u = users[i];
    ((float4*)out)[(size_t)i * (EMB / 4) + lane] =
        ((const float4*)ue)[(size_t)u * (EMB / 4) + lane];
}

// ---------------------------------------------------------------------------
// out[i] += l2norm(ego[users[i]])   (warp per row, shfl reduce)
// ---------------------------------------------------------------------------
__global__ void k_out_accum(const int* __restrict__ users, float* __restrict__ out, int batch) {
    int t = blockIdx.x * blockDim.x + threadIdx.x;
    int i = t >> 5, lane = t & 31;
    if (i >= batch) return;
    int u = users[i];
    float2 x = ((const float2*)(g_ego + (size_t)u * EMB))[lane];
    float ss = x.x * x.x + x.y * x.y;
    #pragma unroll
    for (int off = 16; off; off >>= 1) ss += __shfl_xor_sync(0xffffffffu, ss, off);
    float inv = 1.0f / fmaxf(sqrtf(ss), 1e-12f);
    float2* o = (float2*)(out + (size_t)i * EMB);
    float2 cur = o[lane];
    cur.x += x.x * inv;
    cur.y += x.y * inv;
    o[lane] = cur;
}

// ---------------------------------------------------------------------------
extern "C" void kernel_launch(void* const* d_in, const int* in_sizes, int n_in,
                              void* d_out, int out_size) {
    const int*   users = (const int*)d_in[0];
    const int*   rows  = (const int*)d_in[1];
    const int*   cols  = (const int*)d_in[2];
    const float* vals  = (const float*)d_in[3];
    const float* ue    = (const float*)d_in[4];
    const float* ie    = (const float*)d_in[5];
    const float* Ws[3] = {(const float*)d_in[6], (const float*)d_in[8],  (const float*)d_in[10]};
    const float* bs[3] = {(const float*)d_in[7], (const float*)d_in[9],  (const float*)d_in[11]};
    int batch = in_sizes[0];
    int nnz   = in_sizes[1];
    float* out = (float*)d_out;

    const int nt4 = N_TOT * EMB / 4;

    k_init_ego<<<(nt4 + 255) / 256, 256>>>(ue, ie);
    k_out_init<<<(batch * 16 + 255) / 256, 256>>>(users, ue, out, batch);

    for (int l = 0; l < 3; l++) {
        k_zero_side<<<(nt4 + 255) / 256, 256>>>();
        long long spmm_threads = (long long)nnz * 16;
        k_spmm<<<(unsigned)((spmm_threads + 255) / 256), 256>>>(rows, cols, vals, nnz);
        k_gemm_act<<<(N_TOT + 31) / 32, 256>>>(Ws[l], bs[l]);
        k_out_accum<<<(batch * 32 + 255) / 256, 256>>>(users, out, batch);
    }
}

// round 11
// speedup vs baseline: 2.0008x; 1.9682x over previous
#include <cuda_runtime.h>

#define N_USER 50000
#define N_ITEM 100000
#define N_TOT  150000
#define EMB    64

// Scratch (allocation-free rule: __device__ globals)
__device__ float g_ego[(size_t)N_TOT * EMB];   // 38.4 MB
__device__ float g_side[(size_t)N_TOT * EMB];  // 38.4 MB

// ---------------------------------------------------------------------------
// ego = concat(user_emb, item_emb)   (float4 vectorized copy)
// ---------------------------------------------------------------------------
__global__ void k_init_ego(const float* __restrict__ ue, const float* __restrict__ ie) {
    size_t i = (size_t)blockIdx.x * blockDim.x + threadIdx.x;
    const size_t nu4 = (size_t)N_USER * EMB / 4;
    const size_t nt4 = (size_t)N_TOT * EMB / 4;
    if (i >= nt4) return;
    float4 v = (i < nu4) ? ((const float4*)ue)[i] : ((const float4*)ie)[i - nu4];
    ((float4*)g_ego)[i] = v;
}

__global__ void k_zero_side() {
    size_t i = (size_t)blockIdx.x * blockDim.x + threadIdx.x;
    const size_t nt4 = (size_t)N_TOT * EMB / 4;
    if (i < nt4) ((float4*)g_side)[i] = make_float4(0.f, 0.f, 0.f, 0.f);
}

// ---------------------------------------------------------------------------
// SpMM scatter: side[rows[e]] += vals[e] * ego[cols[e]]
// Warp-cooperative: each lane loads ONE edge's metadata (coalesced LDG),
// then 16 iterations process 2 edges each (lanes 0-15 edge 2j, lanes 16-31
// edge 2j+1) with shfl broadcast, float4 gather, and red.global.add.v4.f32.
// Metadata LDG issues per edge: 48 -> 3 (coalesced).
// ---------------------------------------------------------------------------
__global__ void k_spmm(const int* __restrict__ rows, const int* __restrict__ cols,
                       const float* __restrict__ vals, int nnz) {
    int warp_id = (blockIdx.x * blockDim.x + threadIdx.x) >> 5;
    int lane = threadIdx.x & 31;
    int e0 = warp_id * 32;
    if (e0 >= nnz) return;

    int e = e0 + lane;
    bool ok = (e < nnz);
    int   r = ok ? __ldg(rows + e) : 0;
    int   c = ok ? __ldg(cols + e) : 0;
    float v = ok ? __ldg(vals + e) : 0.0f;   // v=0 padding: RED of 0 is a no-op

    int half = lane >> 4;     // 0: lanes 0-15, 1: lanes 16-31
    int l4   = lane & 15;     // float4 slot within the edge's 64-float row

    #pragma unroll 4
    for (int j = 0; j < 16; j++) {
        int   src = 2 * j + half;
        int   rj = __shfl_sync(0xffffffffu, r, src);
        int   cj = __shfl_sync(0xffffffffu, c, src);
        float vj = __shfl_sync(0xffffffffu, v, src);
        float4 x = ((const float4*)(g_ego + (size_t)cj * EMB))[l4];
        float* dst = g_side + (size_t)rj * EMB + l4 * 4;
        asm volatile("red.global.add.v4.f32 [%0], {%1, %2, %3, %4};"
                     :: "l"(dst), "f"(vj * x.x), "f"(vj * x.y),
                        "f"(vj * x.z), "f"(vj * x.w)
                     : "memory");
    }
}

// ---------------------------------------------------------------------------
// ego = leaky_relu(side @ W + b, 0.2)   — R1-R4 layout (known-good envelope).
// Block: 256 threads, 32 rows. thread (rs=tid/64, col=tid%64) computes rows
// rs, rs+4, ..., rs+28. sW[k*64+col]: consecutive cols per warp -> conflict-
// free; sR[row][k]: broadcast.
// ---------------------------------------------------------------------------
__global__ void k_gemm_act(const float* __restrict__ W, const float* __restrict__ b) {
    __shared__ float sW[EMB * EMB];
    __shared__ float sR[32][EMB];
    __shared__ float sB[EMB];
    int tid = threadIdx.x;

    for (int i = tid; i < EMB * EMB; i += 256) sW[i] = W[i];
    if (tid < EMB) sB[tid] = b[tid];

    int row0 = blockIdx.x * 32;
    for (int i = tid; i < 32 * EMB / 4; i += 256) {
        int rr = i / (EMB / 4);
        size_t gr = (size_t)row0 + rr;
        float4 v = (gr < N_TOT) ? ((const float4*)(g_side + gr * EMB))[i % (EMB / 4)]
                                : make_float4(0.f, 0.f, 0.f, 0.f);
        ((float4*)sR)[i] = v;
    }
    __syncthreads();

    int col = tid & 63;
    int rs  = tid >> 6;  // 0..3
    #pragma unroll
    for (int j = 0; j < 8; j++) {
        int row = rs + j * 4;
        size_t grow = (size_t)row0 + row;
        if (grow >= N_TOT) continue;
        float acc = sB[col];
        #pragma unroll
        for (int k = 0; k < EMB; k++) acc += sR[row][k] * sW[k * EMB + col];
        acc = (acc > 0.f) ? acc : 0.2f * acc;
        g_ego[grow * EMB + col] = acc;
    }
}

// ---------------------------------------------------------------------------
// out[i] = user_emb[users[i]]   (16 threads/row, float4)
// ---------------------------------------------------------------------------
__global__ void k_out_init(const int* __restrict__ users, const float* __restrict__ ue,
                           float* __restrict__ out, int batch) {
    int t = blockIdx.x * blockDim.x + threadIdx.x;
    int i = t >> 4, lane = t & 15;
    if (i >= batch) return;
    int u = users[i];
    ((float4*)out)[(size_t)i * (EMB / 4) + lane] =
        ((const float4*)ue)[(size_t)u * (EMB / 4) + lane];
}

// ---------------------------------------------------------------------------
// out[i] += l2norm(ego[users[i]])   (warp per row, shfl reduce)
// ---------------------------------------------------------------------------
__global__ void k_out_accum(const int* __restrict__ users, float* __restrict__ out, int batch) {
    int t = blockIdx.x * blockDim.x + threadIdx.x;
    int i = t >> 5, lane = t & 31;
    if (i >= batch) return;
    int u = users[i];
    float2 x = ((const float2*)(g_ego + (size_t)u * EMB))[lane];
    float ss = x.x * x.x + x.y * x.y;
    #pragma unroll
    for (int off = 16; off; off >>= 1) ss += __shfl_xor_sync(0xffffffffu, ss, off);
    float inv = 1.0f / fmaxf(sqrtf(ss), 1e-12f);
    float2* o = (float2*)(out + (size_t)i * EMB);
    float2 cur = o[lane];
    cur.x += x.x * inv;
    cur.y += x.y * inv;
    o[lane] = cur;
}

// ---------------------------------------------------------------------------
extern "C" void kernel_launch(void* const* d_in, const int* in_sizes, int n_in,
                              void* d_out, int out_size) {
    const int*   users = (const int*)d_in[0];
    const int*   rows  = (const int*)d_in[1];
    const int*   cols  = (const int*)d_in[2];
    const float* vals  = (const float*)d_in[3];
    const float* ue    = (const float*)d_in[4];
    const float* ie    = (const float*)d_in[5];
    const float* Ws[3] = {(const float*)d_in[6], (const float*)d_in[8],  (const float*)d_in[10]};
    const float* bs[3] = {(const float*)d_in[7], (const float*)d_in[9],  (const float*)d_in[11]};
    int batch = in_sizes[0];
    int nnz   = in_sizes[1];
    float* out = (float*)d_out;

    const int nt4 = N_TOT * EMB / 4;

    k_init_ego<<<(nt4 + 255) / 256, 256>>>(ue, ie);
    k_out_init<<<(batch * 16 + 255) / 256, 256>>>(users, ue, out, batch);

    int nwarps = (nnz + 31) / 32;
    int spmm_blocks = (nwarps * 32 + 255) / 256;

    for (int l = 0; l < 3; l++) {
        k_zero_side<<<(nt4 + 255) / 256, 256>>>();
        k_spmm<<<spmm_blocks, 256>>>(rows, cols, vals, nnz);
        k_gemm_act<<<(N_TOT + 31) / 32, 256>>>(Ws[l], bs[l]);
        k_out_accum<<<(batch * 32 + 255) / 256, 256>>>(users, out, batch);
    }
}